// round 8
// baseline (speedup 1.0000x reference)
#include <cuda_runtime.h>
#include <cstdint>
#include <math.h>

#define BB 65536
#define FDIM 267
#define HDIM 256
#define LDIM 64
#define KCODE 1024

// pair-array K strides (u32 = 2 fp16 K-elems), padded to 16-u32 chunk multiples
#define KU1 272   // fc1: K=534 -> NC=17
#define KU2 128   // K=256 -> NC=8
#define KU4 176   // fc4: K=331 -> NC=11
#define KUM 32    // mu pairs (L=64)

// ---------------- scratch (device globals) ----------------
__device__ uint32_t g_s1h[BB * KU1], g_s1l[BB * KU1];   // x||c pre-split
__device__ uint32_t g_s2h[BB * KU4], g_s2l[BB * KU4];   // q||c pre-split
__device__ uint32_t g_h1h[BB * KU2], g_h1l[BB * KU2];
__device__ uint32_t g_h2h[BB * KU2], g_h2l[BB * KU2];
__device__ uint32_t g_muh[BB * KUM], g_mul[BB * KUM];
__device__ float    g_mu[BB * LDIM];
__device__ int      g_idx[BB];
__device__ float    g_esq[KCODE];
__device__ int      g_counts[KCODE];
__device__ float    g_partials[BB / 8];
__device__ uint32_t g_eth[KCODE * 32], g_etl[KCODE * 32];  // codebook pairs [code][l/2]
// weight pair arrays (rows padded to gridx*128, K padded to chunk mult)
__device__ uint32_t g_w1h[256 * KU1], g_w1l[256 * KU1];
__device__ uint32_t g_w2h[256 * KU2], g_w2l[256 * KU2];
__device__ uint32_t g_w3h[256 * KU2], g_w3l[256 * KU2];
__device__ uint32_t g_wmh[128 * KU2], g_wml[128 * KU2];
__device__ uint32_t g_w4h[256 * KU4], g_w4l[256 * KU4];
__device__ uint32_t g_w5h[256 * KU2], g_w5l[256 * KU2];
__device__ uint32_t g_w6h[256 * KU2], g_w6l[256 * KU2];
__device__ uint32_t g_woh[384 * KU2], g_wol[384 * KU2];

// ---------------- helpers ----------------
__device__ __forceinline__ float hi32(float a) {
    return __uint_as_float(__float_as_uint(a) & 0xFFFFE000u);
}
__device__ __forceinline__ uint32_t packh(float x, float y) {
    uint32_t d;
    asm("cvt.rn.f16x2.f32 %0, %1, %2;" : "=r"(d) : "f"(y), "f"(x));
    return d;
}
__device__ __forceinline__ uint32_t split_pack(float a, float b, uint32_t& lo) {
    float ha = hi32(a), hb = hi32(b);
    lo = packh(a - ha, b - hb);
    return packh(ha, hb);
}
__device__ __forceinline__ uint32_t smem_u32(const void* p) {
    uint32_t a;
    asm("{ .reg .u64 t; cvta.to.shared.u64 t, %1; cvt.u32.u64 %0, t; }" : "=r"(a) : "l"(p));
    return a;
}
__device__ __forceinline__ void ldm_x4(uint32_t* d, uint32_t a) {
    asm volatile("ldmatrix.sync.aligned.m8n8.x4.shared.b16 {%0,%1,%2,%3}, [%4];"
        : "=r"(d[0]), "=r"(d[1]), "=r"(d[2]), "=r"(d[3]) : "r"(a));
}
__device__ __forceinline__ void mma16(float* d, const uint32_t* a, const uint32_t* b) {
    asm volatile(
        "mma.sync.aligned.m16n8k16.row.col.f32.f16.f16.f32 "
        "{%0,%1,%2,%3},{%4,%5,%6,%7},{%8,%9},{%0,%1,%2,%3};"
        : "+f"(d[0]), "+f"(d[1]), "+f"(d[2]), "+f"(d[3])
        : "r"(a[0]), "r"(a[1]), "r"(a[2]), "r"(a[3]), "r"(b[0]), "r"(b[1]));
}
__device__ __forceinline__ void cpa16(uint32_t sa, const void* g) {
    asm volatile("cp.async.cg.shared.global [%0], [%1], 16;" :: "r"(sa), "l"(g) : "memory");
}
#define CPA_COMMIT() asm volatile("cp.async.commit_group;" ::: "memory")
#define CPA_WAIT(n)  asm volatile("cp.async.wait_group %0;" :: "n"(n) : "memory")

// ---------------- fp16x3 HMMA GEMM on pre-split pair arrays ----------------
// C[M,N] = act(A * W^T + b). 128x128 CTA tile, BK=32 (16 u32), 16 warps (4m x 4n).
// smem per buf (u32): Ahi[128][20] | Alo | Bhi | Blo = 10240; 2 bufs = 81920 B.
__global__ void __launch_bounds__(512, 1) mma_gemm(
    const uint32_t* __restrict__ Ahi, const uint32_t* __restrict__ Alo, int KAu,
    const uint32_t* __restrict__ Whi, const uint32_t* __restrict__ Wlo,
    const float* __restrict__ bias,
    float* __restrict__ Cf, uint32_t* __restrict__ Chi, uint32_t* __restrict__ Clo,
    int N, int NC, int relu)
{
    extern __shared__ uint32_t smu[];

    const int tid = threadIdx.x, lane = tid & 31, wid = tid >> 5;
    const int m0 = blockIdx.y * 128, bn = blockIdx.x * 128;
    const int wm0 = (wid >> 2) * 32, wn0 = (wid & 3) * 32;
    const int r = lane >> 2, kq = lane & 3;

    // loader mapping: 512 threads = 128 rows x 4 segs of 16B
    const int lrow = tid >> 2, seg = tid & 3;
    const uint32_t sbase = smem_u32(smu);
    const uint32_t sd0 = sbase + 4u * (lrow * 20 + seg * 4);
    const uint32_t* pAh = Ahi + (size_t)(m0 + lrow) * KAu + seg * 4;
    const uint32_t* pAl = Alo + (size_t)(m0 + lrow) * KAu + seg * 4;
    const uint32_t* pBh = Whi + (size_t)(bn + lrow) * KAu + seg * 4;
    const uint32_t* pBl = Wlo + (size_t)(bn + lrow) * KAu + seg * 4;

    // ldmatrix lane addresses (buffer 0)
    const int g = lane >> 3, lr = lane & 7;
    uint32_t aA[2][2], aB[2][2];
    #pragma unroll
    for (int mt = 0; mt < 2; mt++) {
        const uint32_t row = wm0 + mt * 16 + (g & 1) * 8 + lr;
        const uint32_t col = (g >> 1) * 4;
        #pragma unroll
        for (int ks = 0; ks < 2; ks++)
            aA[mt][ks] = sbase + 4u * (row * 20 + col + ks * 8);
    }
    #pragma unroll
    for (int np = 0; np < 2; np++) {
        const uint32_t n = wn0 + (2 * np + (g >> 1)) * 8 + lr;
        const uint32_t col = (g & 1) * 4;
        #pragma unroll
        for (int ks = 0; ks < 2; ks++)
            aB[np][ks] = sbase + 4u * (5120 + n * 20 + col + ks * 8);
    }

    float acc[2][4][4];
    #pragma unroll
    for (int i = 0; i < 2; i++)
        #pragma unroll
        for (int j = 0; j < 4; j++)
            #pragma unroll
            for (int e = 0; e < 4; e++) acc[i][j][e] = 0.f;

    auto copy_chunk = [&](int c) {
        const uint32_t d = sd0 + (uint32_t)(c & 1) * 40960u;
        const size_t go = (size_t)c * 16;
        cpa16(d,          pAh + go);
        cpa16(d + 10240u, pAl + go);
        cpa16(d + 20480u, pBh + go);
        cpa16(d + 30720u, pBl + go);
        CPA_COMMIT();
    };
    auto compute = [&]() {
        #pragma unroll
        for (int ks = 0; ks < 2; ks++) {
            uint32_t ah[2][4], al[2][4], bh[4][2], bl[4][2];
            ldm_x4(ah[0], aA[0][ks]);
            ldm_x4(ah[1], aA[1][ks]);
            ldm_x4(al[0], aA[0][ks] + 10240u);
            ldm_x4(al[1], aA[1][ks] + 10240u);
            ldm_x4(&bh[0][0], aB[0][ks]);
            ldm_x4(&bh[2][0], aB[1][ks]);
            ldm_x4(&bl[0][0], aB[0][ks] + 10240u);
            ldm_x4(&bl[2][0], aB[1][ks] + 10240u);
            #pragma unroll
            for (int mt = 0; mt < 2; mt++)
                #pragma unroll
                for (int nt = 0; nt < 4; nt++) {
                    mma16(acc[mt][nt], ah[mt], bh[nt]);
                    mma16(acc[mt][nt], ah[mt], bl[nt]);
                    mma16(acc[mt][nt], al[mt], bh[nt]);
                }
        }
    };

    copy_chunk(0);
    int32_t dshift = 40960;
    for (int c = 0; c < NC; c++) {
        if (c + 1 < NC) { copy_chunk(c + 1); CPA_WAIT(1); }
        else            { CPA_WAIT(0); }
        __syncthreads();
        compute();
        __syncthreads();
        if (c + 1 < NC) {
            #pragma unroll
            for (int mt = 0; mt < 2; mt++)
                #pragma unroll
                for (int ks = 0; ks < 2; ks++) { aA[mt][ks] += dshift; aB[mt][ks] += dshift; }
            dshift = -dshift;
        }
    }

    // epilogue
    const bool evenN = (N & 1) == 0;
    const int NU = N >> 1;
    #pragma unroll
    for (int mt = 0; mt < 2; mt++) {
        #pragma unroll
        for (int q = 0; q < 2; q++) {
            const int row = m0 + wm0 + mt * 16 + q * 8 + r;
            #pragma unroll
            for (int nt = 0; nt < 4; nt++) {
                const int n = bn + wn0 + nt * 8 + 2 * kq;
                float v0 = acc[mt][nt][q * 2 + 0];
                float v1 = acc[mt][nt][q * 2 + 1];
                if (n + 1 < N) {
                    float o0 = v0 + bias[n];
                    float o1 = v1 + bias[n + 1];
                    if (relu) { o0 = fmaxf(o0, 0.f); o1 = fmaxf(o1, 0.f); }
                    if (Chi) {
                        uint32_t l; uint32_t h = split_pack(o0, o1, l);
                        Chi[(size_t)row * NU + (n >> 1)] = h;
                        Clo[(size_t)row * NU + (n >> 1)] = l;
                    }
                    if (Cf) {
                        if (evenN) {
                            float2 p; p.x = o0; p.y = o1;
                            *(float2*)&Cf[(size_t)row * N + n] = p;
                        } else {
                            Cf[(size_t)row * N + n] = o0;
                            Cf[(size_t)row * N + n + 1] = o1;
                        }
                    }
                } else if (n < N && Cf) {
                    float o0 = v0 + bias[n];
                    if (relu) o0 = fmaxf(o0, 0.f);
                    Cf[(size_t)row * N + n] = o0;
                }
            }
        }
    }
}

// ---------------- VQ argmin via fp16x3 HMMA + ldmatrix (pre-split pairs) ----------------
// 128 rows/CTA, 8 code-tiles of 128, K=64; score = esq[k] - 2*mu.e_k ; ties -> lowest index.
__global__ void __launch_bounds__(256, 1) vq_mma()
{
    extern __shared__ uint32_t smv[];
    uint32_t* Mh = smv;             // [128][36]
    uint32_t* Ml = smv + 4608;
    uint32_t* Eh = smv + 9216;
    uint32_t* El = smv + 13824;
    float* esq_s = (float*)(smv + 18432);

    __shared__ float sbest[8][2][2][8];
    __shared__ int   sidx[8][2][2][8];

    const int tid = threadIdx.x, lane = tid & 31, wid = tid >> 5;
    const int m0 = blockIdx.x * 128;
    const int wm0 = (wid >> 1) * 32, wn0 = (wid & 1) * 64;
    const int r = lane >> 2, kq = lane & 3;

    const uint32_t sbase = smem_u32(smv);
    const int g = lane >> 3, lr = lane & 7;
    uint32_t aM[2], aE[4];
    #pragma unroll
    for (int mt = 0; mt < 2; mt++) {
        const uint32_t row = wm0 + mt * 16 + (g & 1) * 8 + lr;
        aM[mt] = sbase + 4u * (row * 36 + (g >> 1) * 4);
    }
    #pragma unroll
    for (int np = 0; np < 4; np++) {
        const uint32_t n = wn0 + (2 * np + (g >> 1)) * 8 + lr;
        aE[np] = sbase + 4u * (9216 + n * 36 + (g & 1) * 4);
    }

    // mu pairs: 16 passes of 8 rows
    #pragma unroll
    for (int ps = 0; ps < 16; ps++) {
        const int row = ps * 8 + wid;
        Mh[row * 36 + lane] = g_muh[(size_t)(m0 + row) * KUM + lane];
        Ml[row * 36 + lane] = g_mul[(size_t)(m0 + row) * KUM + lane];
    }
    for (int i = tid; i < KCODE; i += 256) esq_s[i] = g_esq[i];

    float best[2][2];
    int   bidx[2][2];
    #pragma unroll
    for (int i = 0; i < 2; i++)
        #pragma unroll
        for (int j = 0; j < 2; j++) { best[i][j] = 3.4e38f; bidx[i][j] = 0; }

    uint32_t uh[16], ul[16];
    for (int ct = 0; ct < 8; ct++) {
        #pragma unroll
        for (int ps = 0; ps < 16; ps++) {
            const int row = ps * 8 + wid;
            uh[ps] = g_eth[(size_t)(ct * 128 + row) * 32 + lane];
            ul[ps] = g_etl[(size_t)(ct * 128 + row) * 32 + lane];
        }
        __syncthreads();   // prior compute done reading E (also covers mu/esq on ct=0)
        #pragma unroll
        for (int ps = 0; ps < 16; ps++) {
            const int row = ps * 8 + wid;
            Eh[row * 36 + lane] = uh[ps];
            El[row * 36 + lane] = ul[ps];
        }
        __syncthreads();

        float acc[2][8][4];
        #pragma unroll
        for (int i = 0; i < 2; i++)
            #pragma unroll
            for (int j = 0; j < 8; j++)
                #pragma unroll
                for (int e = 0; e < 4; e++) acc[i][j][e] = 0.f;

        #pragma unroll
        for (int ks = 0; ks < 4; ks++) {
            const uint32_t ko = ks * 32u;
            uint32_t ah[2][4], al[2][4], bh[8][2], bl[8][2];
            ldm_x4(ah[0], aM[0] + ko);
            ldm_x4(ah[1], aM[1] + ko);
            ldm_x4(al[0], aM[0] + ko + 18432u);
            ldm_x4(al[1], aM[1] + ko + 18432u);
            #pragma unroll
            for (int np = 0; np < 4; np++) {
                ldm_x4(&bh[2 * np][0], aE[np] + ko);
                ldm_x4(&bl[2 * np][0], aE[np] + ko + 18432u);
            }
            #pragma unroll
            for (int mt = 0; mt < 2; mt++)
                #pragma unroll
                for (int nt = 0; nt < 8; nt++) {
                    mma16(acc[mt][nt], ah[mt], bh[nt]);
                    mma16(acc[mt][nt], ah[mt], bl[nt]);
                    mma16(acc[mt][nt], al[mt], bh[nt]);
                }
        }

        #pragma unroll
        for (int mt = 0; mt < 2; mt++)
            #pragma unroll
            for (int q = 0; q < 2; q++)
                #pragma unroll
                for (int nt = 0; nt < 8; nt++)
                    #pragma unroll
                    for (int e = 0; e < 2; e++) {
                        const int code = ct * 128 + wn0 + nt * 8 + 2 * kq + e;
                        const float sc = esq_s[code] - 2.f * acc[mt][nt][q * 2 + e];
                        if (sc < best[mt][q]) { best[mt][q] = sc; bidx[mt][q] = code; }
                    }
        __syncthreads();
    }

    #pragma unroll
    for (int mt = 0; mt < 2; mt++)
        #pragma unroll
        for (int q = 0; q < 2; q++) {
            float b = best[mt][q]; int ix = bidx[mt][q];
            #pragma unroll
            for (int s = 1; s <= 2; s <<= 1) {
                const float ob = __shfl_xor_sync(0xffffffffu, b, s);
                const int   oi = __shfl_xor_sync(0xffffffffu, ix, s);
                if (ob < b || (ob == b && oi < ix)) { b = ob; ix = oi; }
            }
            if (kq == 0) { sbest[wid][mt][q][r] = b; sidx[wid][mt][q][r] = ix; }
        }
    __syncthreads();

    if ((wid & 1) == 0 && kq == 0) {
        #pragma unroll
        for (int mt = 0; mt < 2; mt++)
            #pragma unroll
            for (int q = 0; q < 2; q++) {
                float b0 = sbest[wid][mt][q][r];     int i0 = sidx[wid][mt][q][r];
                float b1 = sbest[wid + 1][mt][q][r]; int i1 = sidx[wid + 1][mt][q][r];
                int ix = (b1 < b0 || (b1 == b0 && i1 < i0)) ? i1 : i0;
                g_idx[m0 + wm0 + mt * 16 + r + q * 8] = ix;
            }
    }
}

// ---------------- prep kernels ----------------
__global__ void wsplit(const float* __restrict__ W, uint32_t* __restrict__ hi,
                       uint32_t* __restrict__ lo, int N, int K, int KU, int total)
{
    int i = blockIdx.x * 256 + threadIdx.x;
    if (i >= total) return;
    int n = i / KU, j = i - n * KU;
    int k0 = 2 * j;
    float a = (n < N && k0 < K) ? W[(size_t)n * K + k0] : 0.f;
    float b = (n < N && k0 + 1 < K) ? W[(size_t)n * K + k0 + 1] : 0.f;
    uint32_t l; uint32_t h = split_pack(a, b, l);
    hi[i] = h; lo[i] = l;
}
// x||c -> s1 pairs (K=534 concat, KU1=272)
__global__ void split_xc(const float* __restrict__ x, const float* __restrict__ c)
{
    int i = blockIdx.x * 256 + threadIdx.x;
    if (i >= BB * KU1) return;
    int row = i / KU1, j = i - row * KU1;
    int k0 = 2 * j;
    float a = 0.f, b = 0.f;
    if (k0 < 534)     a = (k0 < FDIM) ? x[(size_t)row * FDIM + k0] : c[(size_t)row * FDIM + k0 - FDIM];
    if (k0 + 1 < 534) b = (k0 + 1 < FDIM) ? x[(size_t)row * FDIM + k0 + 1] : c[(size_t)row * FDIM + k0 + 1 - FDIM];
    uint32_t l; uint32_t h = split_pack(a, b, l);
    g_s1h[i] = h; g_s1l[i] = l;
}
// c-part of s2 pairs (j in [32, KU4)), k = 2j-64 into c
__global__ void split_c4(const float* __restrict__ c)
{
    int i = blockIdx.x * 256 + threadIdx.x;
    const int JW = KU4 - 32;
    if (i >= BB * JW) return;
    int row = i / JW, j = 32 + (i - row * JW);
    int k0 = 2 * j - 64;
    float a = (k0 < FDIM) ? c[(size_t)row * FDIM + k0] : 0.f;
    float b = (k0 + 1 < FDIM) ? c[(size_t)row * FDIM + k0 + 1] : 0.f;
    uint32_t l; uint32_t h = split_pack(a, b, l);
    g_s2h[(size_t)row * KU4 + j] = h;
    g_s2l[(size_t)row * KU4 + j] = l;
}
// transposed codebook pairs: [code][l/2]
__global__ void et_split(const float* __restrict__ embed)
{
    int i = blockIdx.x * 256 + threadIdx.x;
    if (i >= KCODE * 32) return;
    int code = i >> 5, j = i & 31;
    float a = embed[(2 * j) * KCODE + code];
    float b = embed[(2 * j + 1) * KCODE + code];
    uint32_t l; uint32_t h = split_pack(a, b, l);
    g_eth[i] = h; g_etl[i] = l;
}
__global__ void esq_kernel(const float* __restrict__ embed) {
    int k = blockIdx.x * blockDim.x + threadIdx.x;
    if (k < KCODE) {
        float s = 0.f;
        #pragma unroll 8
        for (int l = 0; l < LDIM; l++) { float e = embed[l * KCODE + k]; s += e * e; }
        g_esq[k] = s;
    }
}
__global__ void zero_counts_kernel() {
    int i = blockIdx.x * blockDim.x + threadIdx.x;
    if (i < KCODE) g_counts[i] = 0;
}

// gather: q pairs into s2 (j<32), loss partials, histogram
__global__ void __launch_bounds__(256) gather_loss_kernel(const float* __restrict__ embed) {
    __shared__ float ps[8];
    const int w = threadIdx.x >> 5, lane = threadIdx.x & 31;
    const int row = blockIdx.x * 8 + w;
    const int idx = g_idx[row];
    float e0 = embed[(2 * lane) * KCODE + idx];
    float e1 = embed[(2 * lane + 1) * KCODE + idx];
    uint32_t l; uint32_t h = split_pack(e0, e1, l);
    g_s2h[(size_t)row * KU4 + lane] = h;
    g_s2l[(size_t)row * KU4 + lane] = l;
    float2 m = *(const float2*)&g_mu[(size_t)row * LDIM + 2 * lane];
    float d0 = e0 - m.x, d1 = e1 - m.y;
    float s = d0 * d0 + d1 * d1;
    #pragma unroll
    for (int off = 16; off; off >>= 1) s += __shfl_down_sync(0xffffffffu, s, off);
    if (lane == 0) { ps[w] = s; atomicAdd(&g_counts[idx], 1); }
    __syncthreads();
    if (threadIdx.x == 0) {
        float t = 0.f;
        #pragma unroll
        for (int i = 0; i < 8; i++) t += ps[i];
        g_partials[blockIdx.x] = t;
    }
}

__global__ void __launch_bounds__(256) finalize_kernel(float* __restrict__ out) {
    __shared__ float red[256];
    const int t = threadIdx.x;
    float s = 0.f;
    for (int i = t; i < BB / 8; i += 256) s += g_partials[i];
    red[t] = s;
    for (int st = 128; st > 0; st >>= 1) { __syncthreads(); if (t < st) red[t] += red[t + st]; }
    __syncthreads();
    float loss = red[0] / (float)((size_t)BB * LDIM);
    __syncthreads();
    float e = 0.f;
    for (int k = t; k < KCODE; k += 256) {
        float p = (float)g_counts[k] / (float)BB;
        e += p * logf(p + 1e-10f);
    }
    red[t] = e;
    for (int st = 128; st > 0; st >>= 1) { __syncthreads(); if (t < st) red[t] += red[t + st]; }
    __syncthreads();
    if (t == 0) {
        out[(size_t)BB * FDIM] = loss;
        out[(size_t)BB * FDIM + 1] = expf(-red[0]);
    }
}

// ---------------- host launcher ----------------
#define SYM(v, s) cudaGetSymbolAddress((void**)&v, s)

extern "C" void kernel_launch(void* const* d_in, const int* in_sizes, int n_in,
                              void* d_out, int out_size)
{
    const float* x     = (const float*)d_in[0];
    const float* c     = (const float*)d_in[1];
    const float* fc1_w = (const float*)d_in[2];
    const float* fc1_b = (const float*)d_in[3];
    const float* fc2_w = (const float*)d_in[4];
    const float* fc2_b = (const float*)d_in[5];
    const float* fc3_w = (const float*)d_in[6];
    const float* fc3_b = (const float*)d_in[7];
    const float* mu_w  = (const float*)d_in[8];
    const float* mu_b  = (const float*)d_in[9];
    const float* fc4_w = (const float*)d_in[10];
    const float* fc4_b = (const float*)d_in[11];
    const float* fc5_w = (const float*)d_in[12];
    const float* fc5_b = (const float*)d_in[13];
    const float* fc6_w = (const float*)d_in[14];
    const float* fc6_b = (const float*)d_in[15];
    const float* out_w = (const float*)d_in[16];
    const float* out_b = (const float*)d_in[17];
    const float* embed = (const float*)d_in[18];
    float* out = (float*)d_out;

    uint32_t *s1h, *s1l, *s2h, *s2l, *h1h, *h1l, *h2h, *h2l, *muh, *mul;
    uint32_t *w1h, *w1l, *w2h, *w2l, *w3h, *w3l, *wmh, *wml;
    uint32_t *w4h, *w4l, *w5h, *w5l, *w6h, *w6l, *woh, *wol;
    float* mu;
    SYM(s1h, g_s1h); SYM(s1l, g_s1l); SYM(s2h, g_s2h); SYM(s2l, g_s2l);
    SYM(h1h, g_h1h); SYM(h1l, g_h1l); SYM(h2h, g_h2h); SYM(h2l, g_h2l);
    SYM(muh, g_muh); SYM(mul, g_mul); SYM(mu, g_mu);
    SYM(w1h, g_w1h); SYM(w1l, g_w1l); SYM(w2h, g_w2h); SYM(w2l, g_w2l);
    SYM(w3h, g_w3h); SYM(w3l, g_w3l); SYM(wmh, g_wmh); SYM(wml, g_wml);
    SYM(w4h, g_w4h); SYM(w4l, g_w4l); SYM(w5h, g_w5h); SYM(w5l, g_w5l);
    SYM(w6h, g_w6h); SYM(w6l, g_w6l); SYM(woh, g_woh); SYM(wol, g_wol);

    const int GEMM_SMEM = 2 * 10240 * 4;            // 81920 B
    const int VQ_SMEM   = (18432 + 1024) * 4;       // 77824 B
    cudaFuncSetAttribute(mma_gemm, cudaFuncAttributeMaxDynamicSharedMemorySize, GEMM_SMEM);
    cudaFuncSetAttribute(vq_mma,   cudaFuncAttributeMaxDynamicSharedMemorySize, VQ_SMEM);

    const dim3 blk(512);
    const dim3 g256(2, BB / 128);
    const dim3 g64(1, BB / 128);
    const dim3 g267(3, BB / 128);

    // --- prep: weight/codebook splits (tiny) + activation splits ---
    wsplit<<<(256 * KU1 + 255) / 256, 256>>>(fc1_w, w1h, w1l, 256, 534, KU1, 256 * KU1);
    wsplit<<<(256 * KU2 + 255) / 256, 256>>>(fc2_w, w2h, w2l, 256, 256, KU2, 256 * KU2);
    wsplit<<<(256 * KU2 + 255) / 256, 256>>>(fc3_w, w3h, w3l, 256, 256, KU2, 256 * KU2);
    wsplit<<<(128 * KU2 + 255) / 256, 256>>>(mu_w,  wmh, wml, 64,  256, KU2, 128 * KU2);
    wsplit<<<(256 * KU4 + 255) / 256, 256>>>(fc4_w, w4h, w4l, 256, 331, KU4, 256 * KU4);
    wsplit<<<(256 * KU2 + 255) / 256, 256>>>(fc5_w, w5h, w5l, 256, 256, KU2, 256 * KU2);
    wsplit<<<(256 * KU2 + 255) / 256, 256>>>(fc6_w, w6h, w6l, 256, 256, KU2, 256 * KU2);
    wsplit<<<(384 * KU2 + 255) / 256, 256>>>(out_w, woh, wol, 267, 256, KU2, 384 * KU2);
    et_split<<<(KCODE * 32 + 255) / 256, 256>>>(embed);
    esq_kernel<<<4, 256>>>(embed);
    zero_counts_kernel<<<4, 256>>>();
    split_xc<<<(BB * KU1 + 255) / 256, 256>>>(x, c);
    split_c4<<<(BB * (KU4 - 32) + 255) / 256, 256>>>(c);

    // --- encoder ---
    mma_gemm<<<g256, blk, GEMM_SMEM>>>(s1h, s1l, KU1, w1h, w1l, fc1_b, nullptr, h1h, h1l, HDIM, 17, 1);
    mma_gemm<<<g256, blk, GEMM_SMEM>>>(h1h, h1l, KU2, w2h, w2l, fc2_b, nullptr, h2h, h2l, HDIM, 8, 1);
    mma_gemm<<<g256, blk, GEMM_SMEM>>>(h2h, h2l, KU2, w3h, w3l, fc3_b, nullptr, h1h, h1l, HDIM, 8, 1);
    mma_gemm<<<g64,  blk, GEMM_SMEM>>>(h1h, h1l, KU2, wmh, wml, mu_b, mu, muh, mul, LDIM, 8, 0);

    // --- vector quantizer ---
    vq_mma<<<BB / 128, 256, VQ_SMEM>>>();
    gather_loss_kernel<<<BB / 8, 256>>>(embed);

    // --- decoder ---
    mma_gemm<<<g256, blk, GEMM_SMEM>>>(s2h, s2l, KU4, w4h, w4l, fc4_b, nullptr, h2h, h2l, HDIM, 11, 1);
    mma_gemm<<<g256, blk, GEMM_SMEM>>>(h2h, h2l, KU2, w5h, w5l, fc5_b, nullptr, h1h, h1l, HDIM, 8, 1);
    mma_gemm<<<g256, blk, GEMM_SMEM>>>(h1h, h1l, KU2, w6h, w6l, fc6_b, nullptr, h2h, h2l, HDIM, 8, 1);
    mma_gemm<<<g267, blk, GEMM_SMEM>>>(h2h, h2l, KU2, woh, wol, out_b, out, nullptr, nullptr, FDIM, 8, 0);

    // --- scalars ---
    finalize_kernel<<<1, 256>>>(out);
}

// round 9
// speedup vs baseline: 1.7372x; 1.7372x over previous
#include <cuda_runtime.h>
#include <cstdint>
#include <math.h>

#define BB 65536
#define FDIM 267
#define HDIM 256
#define LDIM 64
#define KCODE 1024

// weight pair strides (uint2 per 2 K-elems), K padded to 16-mult, rows padded to grid
#define KU1 272   // fc1: K=534
#define KU2 128   // K=256
#define KU4 176   // fc4: K=331

// ---------------- scratch (device globals) ----------------
__device__ float g_h1[BB * HDIM];
__device__ float g_h2[BB * HDIM];
__device__ float g_mu[BB * LDIM];
__device__ float g_q[BB * LDIM];
__device__ int   g_idx[BB];
__device__ float g_esq[KCODE];
__device__ int   g_counts[KCODE];
__device__ float g_partials[BB / 8];
__device__ uint32_t g_eth[KCODE * 32], g_etl[KCODE * 32];  // codebook pairs [code][l/2]
__device__ uint2 g_w1i[256 * KU1];
__device__ uint2 g_w2i[256 * KU2];
__device__ uint2 g_w3i[256 * KU2];
__device__ uint2 g_wmi[128 * KU2];
__device__ uint2 g_w4i[256 * KU4];
__device__ uint2 g_w5i[256 * KU2];
__device__ uint2 g_w6i[256 * KU2];
__device__ uint2 g_woi[384 * KU2];

// ---------------- helpers ----------------
__device__ __forceinline__ float hi32(float a) {
    return __uint_as_float(__float_as_uint(a) & 0xFFFFE000u);
}
__device__ __forceinline__ uint32_t packh(float x, float y) {
    uint32_t d;
    asm("cvt.rn.f16x2.f32 %0, %1, %2;" : "=r"(d) : "f"(y), "f"(x));
    return d;
}
__device__ __forceinline__ uint32_t split_pack(float a, float b, uint32_t& lo) {
    float ha = hi32(a), hb = hi32(b);
    lo = packh(a - ha, b - hb);
    return packh(ha, hb);
}
__device__ __forceinline__ uint32_t smem_u32(const void* p) {
    uint32_t a;
    asm("{ .reg .u64 t; cvta.to.shared.u64 t, %1; cvt.u32.u64 %0, t; }" : "=r"(a) : "l"(p));
    return a;
}
__device__ __forceinline__ void ldm_x4(uint32_t* d, uint32_t a) {
    asm volatile("ldmatrix.sync.aligned.m8n8.x4.shared.b16 {%0,%1,%2,%3}, [%4];"
        : "=r"(d[0]), "=r"(d[1]), "=r"(d[2]), "=r"(d[3]) : "r"(a));
}
__device__ __forceinline__ void mma16(float* d, const uint32_t* a, const uint32_t* b) {
    asm volatile(
        "mma.sync.aligned.m16n8k16.row.col.f32.f16.f16.f32 "
        "{%0,%1,%2,%3},{%4,%5,%6,%7},{%8,%9},{%0,%1,%2,%3};"
        : "+f"(d[0]), "+f"(d[1]), "+f"(d[2]), "+f"(d[3])
        : "r"(a[0]), "r"(a[1]), "r"(a[2]), "r"(a[3]), "r"(b[0]), "r"(b[1]));
}

// ---------------- fp16x3 HMMA GEMM: C[M,N] = act([A0|A1][M,K] * Wt^T + b) ----------------
// 128x128 CTA tile, BK=32, 16 warps (4m x 4n), warp tile 32x32.
// A: fp32 global, split on the fly. B: pre-split interleaved uint2 pairs (padded).
// smem u32 per buf: Ahi[128][20] | Alo | Bhi | Blo = 10240; 2 bufs = 81920 B.
__global__ void __launch_bounds__(512, 1) mma_gemm(
    const float* __restrict__ A0, int W0,
    const float* __restrict__ A1, int W1,
    const uint2* __restrict__ Wt, int KUb,
    const float* __restrict__ bias,
    float* __restrict__ C, int N, int K, int relu)
{
    extern __shared__ uint32_t smu[];

    const int tid = threadIdx.x, lane = tid & 31, wid = tid >> 5;
    const int m0 = blockIdx.y * 128, bn = blockIdx.x * 128;
    const int wm0 = (wid >> 2) * 32, wn0 = (wid & 3) * 32;
    const int r = lane >> 2, kq = lane & 3;
    const int NC = (K + 31) >> 5;
    const int prow = tid >> 4;     // 0..31 loader row
    const int pj   = tid & 15;     // u32 col (half2 pair index)
    const bool scalA = (A1 != nullptr);

    // ldmatrix lane addresses (buffer 0)
    const uint32_t sbase = smem_u32(smu);
    const int g = lane >> 3, lr = lane & 7;
    uint32_t aA[2][2], aB[2][2];
    #pragma unroll
    for (int mt = 0; mt < 2; mt++) {
        const uint32_t row = wm0 + mt * 16 + (g & 1) * 8 + lr;
        const uint32_t col = (g >> 1) * 4;
        #pragma unroll
        for (int ks = 0; ks < 2; ks++)
            aA[mt][ks] = sbase + 4u * (row * 20 + col + ks * 8);
    }
    #pragma unroll
    for (int np = 0; np < 2; np++) {
        const uint32_t n = wn0 + (2 * np + (g >> 1)) * 8 + lr;
        const uint32_t col = (g & 1) * 4;
        #pragma unroll
        for (int ks = 0; ks < 2; ks++)
            aB[np][ks] = sbase + 4u * (5120 + n * 20 + col + ks * 8);
    }

    float acc[2][4][4];
    #pragma unroll
    for (int i = 0; i < 2; i++)
        #pragma unroll
        for (int j = 0; j < 4; j++)
            #pragma unroll
            for (int e = 0; e < 4; e++) acc[i][j][e] = 0.f;

    float2 a2[4];
    uint2  bw[4];

    auto prefetch = [&](int c) {
        const int kg = c * 32 + 2 * pj;
        const size_t bo = (size_t)c * 16 + pj;
        #pragma unroll
        for (int p = 0; p < 4; p++) {
            const int row = p * 32 + prow;
            float ax = 0.f, ay = 0.f;
            if (scalA) {
                if (kg < K)
                    ax = (kg < W0) ? A0[(size_t)(m0 + row) * W0 + kg]
                                   : A1[(size_t)(m0 + row) * W1 + (kg - W0)];
                if (kg + 1 < K)
                    ay = (kg + 1 < W0) ? A0[(size_t)(m0 + row) * W0 + kg + 1]
                                       : A1[(size_t)(m0 + row) * W1 + (kg + 1 - W0)];
            } else if (kg < K) {
                float2 t = *(const float2*)&A0[(size_t)(m0 + row) * W0 + kg];
                ax = t.x; ay = t.y;
            }
            a2[p] = make_float2(ax, ay);
            bw[p] = Wt[(size_t)(bn + row) * KUb + bo];
        }
    };
    auto store = [&](int b) {
        uint32_t* base = smu + b * 10240;
        #pragma unroll
        for (int p = 0; p < 4; p++) {
            const int o = (p * 32 + prow) * 20 + pj;
            float hx = hi32(a2[p].x), hy = hi32(a2[p].y);
            base[o]        = packh(hx, hy);
            base[2560 + o] = packh(a2[p].x - hx, a2[p].y - hy);
            base[5120 + o] = bw[p].x;
            base[7680 + o] = bw[p].y;
        }
    };
    auto compute = [&]() {
        #pragma unroll
        for (int ks = 0; ks < 2; ks++) {
            uint32_t ah[2][4], al[2][4], bh[4][2], bl[4][2];
            ldm_x4(ah[0], aA[0][ks]);
            ldm_x4(ah[1], aA[1][ks]);
            ldm_x4(al[0], aA[0][ks] + 10240u);
            ldm_x4(al[1], aA[1][ks] + 10240u);
            ldm_x4(&bh[0][0], aB[0][ks]);
            ldm_x4(&bh[2][0], aB[1][ks]);
            ldm_x4(&bl[0][0], aB[0][ks] + 10240u);
            ldm_x4(&bl[2][0], aB[1][ks] + 10240u);
            #pragma unroll
            for (int mt = 0; mt < 2; mt++)
                #pragma unroll
                for (int nt = 0; nt < 4; nt++) {
                    mma16(acc[mt][nt], ah[mt], bh[nt]);
                    mma16(acc[mt][nt], ah[mt], bl[nt]);
                    mma16(acc[mt][nt], al[mt], bh[nt]);
                }
        }
    };

    prefetch(0); store(0); __syncthreads();
    int32_t dshift = 40960;
    for (int c = 0; c < NC; c++) {
        if (c + 1 < NC) prefetch(c + 1);
        compute();
        if (c + 1 < NC) store((c + 1) & 1);
        __syncthreads();
        if (c + 1 < NC) {
            #pragma unroll
            for (int mt = 0; mt < 2; mt++)
                #pragma unroll
                for (int ks = 0; ks < 2; ks++) { aA[mt][ks] += dshift; aB[mt][ks] += dshift; }
            dshift = -dshift;
        }
    }

    // epilogue: bias + relu, float2 stores when aligned
    const bool evenN = (N & 1) == 0;
    #pragma unroll
    for (int mt = 0; mt < 2; mt++) {
        #pragma unroll
        for (int q = 0; q < 2; q++) {
            const int row = m0 + wm0 + mt * 16 + q * 8 + r;
            #pragma unroll
            for (int nt = 0; nt < 4; nt++) {
                const int n = bn + wn0 + nt * 8 + 2 * kq;
                float v0 = acc[mt][nt][q * 2 + 0];
                float v1 = acc[mt][nt][q * 2 + 1];
                if (n + 1 < N) {
                    float o0 = v0 + bias[n];
                    float o1 = v1 + bias[n + 1];
                    if (relu) { o0 = fmaxf(o0, 0.f); o1 = fmaxf(o1, 0.f); }
                    if (evenN) {
                        float2 p; p.x = o0; p.y = o1;
                        *(float2*)&C[(size_t)row * N + n] = p;
                    } else {
                        C[(size_t)row * N + n] = o0;
                        C[(size_t)row * N + n + 1] = o1;
                    }
                } else if (n < N) {
                    float o0 = v0 + bias[n];
                    if (relu) o0 = fmaxf(o0, 0.f);
                    C[(size_t)row * N + n] = o0;
                }
            }
        }
    }
}

// ---------------- VQ argmin via fp16x3 HMMA + ldmatrix, 512 threads ----------------
// 128 rows/CTA, 8 code-tiles of 128, K=64. 16 warps: 4 row-groups x 4 code-quarters.
// score = esq[k] - 2*mu.e_k ; ties -> lowest index.
__global__ void __launch_bounds__(512, 1) vq_mma()
{
    extern __shared__ uint32_t smv[];
    uint32_t* Mh = smv;             // [128][36]
    uint32_t* Ml = smv + 4608;
    uint32_t* Eh = smv + 9216;
    uint32_t* El = smv + 13824;
    float* esq_s = (float*)(smv + 18432);

    __shared__ float sbest[16][2][2][8];
    __shared__ int   sidx[16][2][2][8];

    const int tid = threadIdx.x, lane = tid & 31, wid = tid >> 5;
    const int m0 = blockIdx.x * 128;
    const int wm0 = (wid >> 2) * 32;
    const int wq  = wid & 3;
    const int wn0 = wq * 32;
    const int r = lane >> 2, kq = lane & 3;

    const uint32_t sbase = smem_u32(smv);
    const int g = lane >> 3, lr = lane & 7;
    uint32_t aM[2], aE[2];
    #pragma unroll
    for (int mt = 0; mt < 2; mt++) {
        const uint32_t row = wm0 + mt * 16 + (g & 1) * 8 + lr;
        aM[mt] = sbase + 4u * (row * 36 + (g >> 1) * 4);
    }
    #pragma unroll
    for (int np = 0; np < 2; np++) {
        const uint32_t n = wn0 + (2 * np + (g >> 1)) * 8 + lr;
        aE[np] = sbase + 4u * (9216 + n * 36 + (g & 1) * 4);
    }

    // mu pairs: 8 passes of 16 rows (split fp32 mu once)
    #pragma unroll
    for (int ps = 0; ps < 8; ps++) {
        const int row = ps * 16 + wid;
        float2 m = *(const float2*)&g_mu[(size_t)(m0 + row) * LDIM + 2 * lane];
        uint32_t l; uint32_t h = split_pack(m.x, m.y, l);
        Mh[row * 36 + lane] = h;
        Ml[row * 36 + lane] = l;
    }
    #pragma unroll
    for (int i = tid; i < KCODE; i += 512) esq_s[i] = g_esq[i];

    float best[2][2];
    int   bidx[2][2];
    #pragma unroll
    for (int i = 0; i < 2; i++)
        #pragma unroll
        for (int j = 0; j < 2; j++) { best[i][j] = 3.4e38f; bidx[i][j] = 0; }

    uint32_t uh[8], ul[8];
    for (int ct = 0; ct < 8; ct++) {
        // prefetch pre-split code tile to regs
        #pragma unroll
        for (int ps = 0; ps < 8; ps++) {
            const int row = ps * 16 + wid;
            uh[ps] = g_eth[(size_t)(ct * 128 + row) * 32 + lane];
            ul[ps] = g_etl[(size_t)(ct * 128 + row) * 32 + lane];
        }
        __syncthreads();   // prior compute done reading E (also covers mu/esq on ct=0)
        #pragma unroll
        for (int ps = 0; ps < 8; ps++) {
            const int row = ps * 16 + wid;
            Eh[row * 36 + lane] = uh[ps];
            El[row * 36 + lane] = ul[ps];
        }
        __syncthreads();

        float acc[2][4][4];
        #pragma unroll
        for (int i = 0; i < 2; i++)
            #pragma unroll
            for (int j = 0; j < 4; j++)
                #pragma unroll
                for (int e = 0; e < 4; e++) acc[i][j][e] = 0.f;

        #pragma unroll
        for (int ks = 0; ks < 4; ks++) {
            const uint32_t ko = ks * 32u;
            uint32_t ah[2][4], al[2][4], bh[4][2], bl[4][2];
            ldm_x4(ah[0], aM[0] + ko);
            ldm_x4(ah[1], aM[1] + ko);
            ldm_x4(al[0], aM[0] + ko + 18432u);
            ldm_x4(al[1], aM[1] + ko + 18432u);
            ldm_x4(&bh[0][0], aE[0] + ko);
            ldm_x4(&bh[2][0], aE[1] + ko);
            ldm_x4(&bl[0][0], aE[0] + ko + 18432u);
            ldm_x4(&bl[2][0], aE[1] + ko + 18432u);
            #pragma unroll
            for (int mt = 0; mt < 2; mt++)
                #pragma unroll
                for (int nt = 0; nt < 4; nt++) {
                    mma16(acc[mt][nt], ah[mt], bh[nt]);
                    mma16(acc[mt][nt], ah[mt], bl[nt]);
                    mma16(acc[mt][nt], al[mt], bh[nt]);
                }
        }

        // score + argmin update (ascending code order; strict < keeps first min)
        #pragma unroll
        for (int mt = 0; mt < 2; mt++)
            #pragma unroll
            for (int q = 0; q < 2; q++)
                #pragma unroll
                for (int nt = 0; nt < 4; nt++)
                    #pragma unroll
                    for (int e = 0; e < 2; e++) {
                        const int code = ct * 128 + wn0 + nt * 8 + 2 * kq + e;
                        const float sc = esq_s[code] - 2.f * acc[mt][nt][q * 2 + e];
                        if (sc < best[mt][q]) { best[mt][q] = sc; bidx[mt][q] = code; }
                    }
        __syncthreads();
    }

    // 1) reduce across the 4 lanes of each quad (same rows, different code subsets)
    #pragma unroll
    for (int mt = 0; mt < 2; mt++)
        #pragma unroll
        for (int q = 0; q < 2; q++) {
            float b = best[mt][q]; int ix = bidx[mt][q];
            #pragma unroll
            for (int s = 1; s <= 2; s <<= 1) {
                const float ob = __shfl_xor_sync(0xffffffffu, b, s);
                const int   oi = __shfl_xor_sync(0xffffffffu, ix, s);
                if (ob < b || (ob == b && oi < ix)) { b = ob; ix = oi; }
            }
            if (kq == 0) { sbest[wid][mt][q][r] = b; sidx[wid][mt][q][r] = ix; }
        }
    __syncthreads();

    // 2) merge the 4 code-quarter warps of each row group, write final index
    if (wq == 0 && kq == 0) {
        #pragma unroll
        for (int mt = 0; mt < 2; mt++)
            #pragma unroll
            for (int q = 0; q < 2; q++) {
                float b0 = sbest[wid][mt][q][r]; int i0 = sidx[wid][mt][q][r];
                #pragma unroll
                for (int w2 = 1; w2 < 4; w2++) {
                    float b1 = sbest[wid + w2][mt][q][r]; int i1 = sidx[wid + w2][mt][q][r];
                    if (b1 < b0 || (b1 == b0 && i1 < i0)) { b0 = b1; i0 = i1; }
                }
                g_idx[m0 + wm0 + mt * 16 + r + q * 8] = i0;
            }
    }
}

// ---------------- prep kernels ----------------
__global__ void wsplit2(const float* __restrict__ W, uint2* __restrict__ out,
                        int N, int K, int KU, int total)
{
    int i = blockIdx.x * 256 + threadIdx.x;
    if (i >= total) return;
    int n = i / KU, j = i - n * KU;
    int k0 = 2 * j;
    float a = (n < N && k0 < K) ? W[(size_t)n * K + k0] : 0.f;
    float b = (n < N && k0 + 1 < K) ? W[(size_t)n * K + k0 + 1] : 0.f;
    uint32_t l; uint32_t h = split_pack(a, b, l);
    out[i] = make_uint2(h, l);
}
// transposed codebook pairs: [code][l/2]
__global__ void et_split(const float* __restrict__ embed)
{
    int i = blockIdx.x * 256 + threadIdx.x;
    if (i >= KCODE * 32) return;
    int code = i >> 5, j = i & 31;
    float a = embed[(2 * j) * KCODE + code];
    float b = embed[(2 * j + 1) * KCODE + code];
    uint32_t l; uint32_t h = split_pack(a, b, l);
    g_eth[i] = h; g_etl[i] = l;
}
__global__ void esq_kernel(const float* __restrict__ embed) {
    int k = blockIdx.x * blockDim.x + threadIdx.x;
    if (k < KCODE) {
        float s = 0.f;
        #pragma unroll 8
        for (int l = 0; l < LDIM; l++) { float e = embed[l * KCODE + k]; s += e * e; }
        g_esq[k] = s;
    }
}
__global__ void zero_counts_kernel() {
    int i = blockIdx.x * blockDim.x + threadIdx.x;
    if (i < KCODE) g_counts[i] = 0;
}

__global__ void __launch_bounds__(256) gather_loss_kernel(const float* __restrict__ embed) {
    __shared__ float ps[8];
    const int w = threadIdx.x >> 5, lane = threadIdx.x & 31;
    const int row = blockIdx.x * 8 + w;
    const int idx = g_idx[row];
    float s = 0.f;
    #pragma unroll
    for (int h = 0; h < 2; h++) {
        int l = lane + 32 * h;
        float e = embed[l * KCODE + idx];
        g_q[(size_t)row * LDIM + l] = e;
        float d = e - g_mu[(size_t)row * LDIM + l];
        s += d * d;
    }
    #pragma unroll
    for (int off = 16; off; off >>= 1) s += __shfl_down_sync(0xffffffffu, s, off);
    if (lane == 0) { ps[w] = s; atomicAdd(&g_counts[idx], 1); }
    __syncthreads();
    if (threadIdx.x == 0) {
        float t = 0.f;
        #pragma unroll
        for (int i = 0; i < 8; i++) t += ps[i];
        g_partials[blockIdx.x] = t;
    }
}

__global__ void __launch_bounds__(256) finalize_kernel(float* __restrict__ out) {
    __shared__ float red[256];
    const int t = threadIdx.x;
    float s = 0.f;
    for (int i = t; i < BB / 8; i += 256) s += g_partials[i];
    red[t] = s;
    for (int st = 128; st > 0; st >>= 1) { __syncthreads(); if (t < st) red[t] += red[t + st]; }
    __syncthreads();
    float loss = red[0] / (float)((size_t)BB * LDIM);
    __syncthreads();
    float e = 0.f;
    for (int k = t; k < KCODE; k += 256) {
        float p = (float)g_counts[k] / (float)BB;
        e += p * logf(p + 1e-10f);
    }
    red[t] = e;
    for (int st = 128; st > 0; st >>= 1) { __syncthreads(); if (t < st) red[t] += red[t + st]; }
    __syncthreads();
    if (t == 0) {
        out[(size_t)BB * FDIM] = loss;
        out[(size_t)BB * FDIM + 1] = expf(-red[0]);
    }
}

// ---------------- host launcher ----------------
#define SYM(v, s) cudaGetSymbolAddress((void**)&v, s)

extern "C" void kernel_launch(void* const* d_in, const int* in_sizes, int n_in,
                              void* d_out, int out_size)
{
    const float* x     = (const float*)d_in[0];
    const float* c     = (const float*)d_in[1];
    const float* fc1_w = (const float*)d_in[2];
    const float* fc1_b = (const float*)d_in[3];
    const float* fc2_w = (const float*)d_in[4];
    const float* fc2_b = (const float*)d_in[5];
    const float* fc3_w = (const float*)d_in[6];
    const float* fc3_b = (const float*)d_in[7];
    const float* mu_w  = (const float*)d_in[8];
    const float* mu_b  = (const float*)d_in[9];
    const float* fc4_w = (const float*)d_in[10];
    const float* fc4_b = (const float*)d_in[11];
    const float* fc5_w = (const float*)d_in[12];
    const float* fc5_b = (const float*)d_in[13];
    const float* fc6_w = (const float*)d_in[14];
    const float* fc6_b = (const float*)d_in[15];
    const float* out_w = (const float*)d_in[16];
    const float* out_b = (const float*)d_in[17];
    const float* embed = (const float*)d_in[18];
    float* out = (float*)d_out;

    float *h1, *h2, *mu, *q;
    uint2 *w1i, *w2i, *w3i, *wmi, *w4i, *w5i, *w6i, *woi;
    SYM(h1, g_h1); SYM(h2, g_h2); SYM(mu, g_mu); SYM(q, g_q);
    SYM(w1i, g_w1i); SYM(w2i, g_w2i); SYM(w3i, g_w3i); SYM(wmi, g_wmi);
    SYM(w4i, g_w4i); SYM(w5i, g_w5i); SYM(w6i, g_w6i); SYM(woi, g_woi);

    const int GEMM_SMEM = 2 * 10240 * 4;            // 81920 B
    const int VQ_SMEM   = (18432 + 1024) * 4;       // 77824 B
    cudaFuncSetAttribute(mma_gemm, cudaFuncAttributeMaxDynamicSharedMemorySize, GEMM_SMEM);
    cudaFuncSetAttribute(vq_mma,   cudaFuncAttributeMaxDynamicSharedMemorySize, VQ_SMEM);

    const dim3 blk(512);
    const dim3 g256(2, BB / 128);
    const dim3 g64(1, BB / 128);
    const dim3 g267(3, BB / 128);

    // prep: weight/codebook splits (tiny)
    wsplit2<<<(256 * KU1 + 255) / 256, 256>>>(fc1_w, w1i, 256, 534, KU1, 256 * KU1);
    wsplit2<<<(256 * KU2 + 255) / 256, 256>>>(fc2_w, w2i, 256, 256, KU2, 256 * KU2);
    wsplit2<<<(256 * KU2 + 255) / 256, 256>>>(fc3_w, w3i, 256, 256, KU2, 256 * KU2);
    wsplit2<<<(128 * KU2 + 255) / 256, 256>>>(mu_w,  wmi, 64,  256, KU2, 128 * KU2);
    wsplit2<<<(256 * KU4 + 255) / 256, 256>>>(fc4_w, w4i, 256, 331, KU4, 256 * KU4);
    wsplit2<<<(256 * KU2 + 255) / 256, 256>>>(fc5_w, w5i, 256, 256, KU2, 256 * KU2);
    wsplit2<<<(256 * KU2 + 255) / 256, 256>>>(fc6_w, w6i, 256, 256, KU2, 256 * KU2);
    wsplit2<<<(384 * KU2 + 255) / 256, 256>>>(out_w, woi, 267, 256, KU2, 384 * KU2);
    et_split<<<(KCODE * 32 + 255) / 256, 256>>>(embed);
    esq_kernel<<<4, 256>>>(embed);
    zero_counts_kernel<<<4, 256>>>();

    // encoder
    mma_gemm<<<g256, blk, GEMM_SMEM>>>(x, FDIM, c, FDIM, w1i, KU1, fc1_b, h1, HDIM, 534, 1);
    mma_gemm<<<g256, blk, GEMM_SMEM>>>(h1, HDIM, nullptr, 0, w2i, KU2, fc2_b, h2, HDIM, HDIM, 1);
    mma_gemm<<<g256, blk, GEMM_SMEM>>>(h2, HDIM, nullptr, 0, w3i, KU2, fc3_b, h1, HDIM, HDIM, 1);
    mma_gemm<<<g64,  blk, GEMM_SMEM>>>(h1, HDIM, nullptr, 0, wmi, KU2, mu_b, mu, LDIM, HDIM, 0);

    // vector quantizer
    vq_mma<<<BB / 128, 512, VQ_SMEM>>>();
    gather_loss_kernel<<<BB / 8, 256>>>(embed);

    // decoder
    mma_gemm<<<g256, blk, GEMM_SMEM>>>(q, LDIM, c, FDIM, w4i, KU4, fc4_b, h2, HDIM, 331, 1);
    mma_gemm<<<g256, blk, GEMM_SMEM>>>(h2, HDIM, nullptr, 0, w5i, KU2, fc5_b, h1, HDIM, HDIM, 1);
    mma_gemm<<<g256, blk, GEMM_SMEM>>>(h1, HDIM, nullptr, 0, w6i, KU2, fc6_b, h2, HDIM, HDIM, 1);
    mma_gemm<<<g267, blk, GEMM_SMEM>>>(h2, HDIM, nullptr, 0, woi, KU2, out_b, out, FDIM, HDIM, 0);

    // scalars
    finalize_kernel<<<1, 256>>>(out);
}